// round 8
// baseline (speedup 1.0000x reference)
#include <cuda_runtime.h>
#include <math.h>

#define BATCH 32
#define NROI 1000
#define NCLS 81
#define MAXI 100
#define NTOT (BATCH * NROI)
#define BPI 8                  // blocks per image
#define RPB 125                // ROIs per block
#define BT 256                 // threads per block
#define MCAP 768               // max compacted entries per image

// compacted per-image lists + tickets (zero-init; reset each run by epilogue)
__device__ float4 g_cbox[NTOT];
__device__ float4 g_cmeta[NTOT];   // {score, cls, origidx, 0}
__device__ int    g_cnt[BATCH];
__device__ int    g_done[BATCH];

struct Epi {
    float uscore[MCAP];
    short uidx[MCAP];
    float box[MCAP * 4];
    float sscore[MCAP];
    short scls[MCAP];
    short bucket[MCAP];
    unsigned char keep[MCAP];
    int   ccount[NCLS];
    int   cstart[NCLS];
    float outbuf[MAXI * 6];
};

union SmemU {
    float probs[RPB * NCLS + 4];   // 40.5 KB tile (+ alignment shift pad)
    Epi   ep;                      // ~27 KB epilogue state
};

__global__ __launch_bounds__(BT, 5)
void det_kernel(const float* __restrict__ rois,
                const float* __restrict__ probs,
                const float* __restrict__ bbox,
                const float* __restrict__ std_dev,
                float* __restrict__ out)
{
    __shared__ SmemU u;
    __shared__ int s_last;

    const int img = blockIdx.x / BPI;
    const int sub = blockIdx.x - img * BPI;
    const int t   = threadIdx.x;
    const int wid = t >> 5;
    const int lane = t & 31;

    // ---------------- Phase 1a: cooperative aligned tile load ----------------
    {
        const size_t s0 = ((size_t)img * NROI + (size_t)sub * RPB) * NCLS;  // elem offset
        const int sh = (int)(s0 & 3);          // misalignment in elements (0..3)
        const int NEL = RPB * NCLS;            // 10125
        const int h = (4 - sh) & 3;            // head elems to reach 16B gmem alignment

        if (t < h) u.probs[sh + t] = probs[s0 + t];
        const int nvec = (NEL - h) >> 2;
        const float4* gp = (const float4*)(probs + s0 + h);
        float4* sp = (float4*)(u.probs + sh + h);   // (sh+h) % 4 == 0 -> 16B aligned
        #pragma unroll 4
        for (int i = t; i < nvec; i += BT) sp[i] = gp[i];
        const int tl = NEL - h - 4 * nvec;
        if (t < tl) { int e = h + 4 * nvec + t; u.probs[sh + e] = probs[s0 + e]; }
        __syncthreads();

        // ------------- Phase 1b: thread-per-ROI argmax from smem -------------
        if (t < RPB) {
            const float* row = u.probs + sh + t * NCLS;   // stride 81: odd, no conflicts
            // 3 interleaved chains over c = 0..80 (81 = 3*27)
            float b0 = row[0]; int i0 = 0;
            float b1 = row[1]; int i1 = 1;
            float b2 = row[2]; int i2 = 2;
            #pragma unroll 13
            for (int c = 3; c < 81; c += 3) {
                float v0 = row[c];
                float v1 = row[c + 1];
                float v2 = row[c + 2];
                if (v0 > b0) { b0 = v0; i0 = c; }
                if (v1 > b1) { b1 = v1; i1 = c + 1; }
                if (v2 > b2) { b2 = v2; i2 = c + 2; }
            }
            // merge, first-max semantics (smaller index wins ties)
            float best = b0; int bi = i0;
            if (b1 > best || (b1 == best && i1 < bi)) { best = b1; bi = i1; }
            if (b2 > best || (b2 == best && i2 < bi)) { best = b2; bi = i2; }

            if (bi > 0 && best >= 0.7f) {
                const int r = sub * RPB + t;
                const size_t gri = (size_t)img * NROI + r;
                const float4 sd = *(const float4*)std_dev;
                const float4 dv = *(const float4*)(bbox + (gri * NCLS + bi) * 4);
                const float4 ro = *(const float4*)(rois + gri * 4);

                float d0 = dv.x * sd.x, d1 = dv.y * sd.y, d2 = dv.z * sd.z, d3 = dv.w * sd.w;
                float hh = ro.z - ro.x;
                float ww = ro.w - ro.y;
                float cy = ro.x + 0.5f * hh + d0 * hh;
                float cx = ro.y + 0.5f * ww + d1 * ww;
                hh *= expf(d2);
                ww *= expf(d3);
                float ny1 = cy - 0.5f * hh;
                float nx1 = cx - 0.5f * ww;
                float ny2 = ny1 + hh;
                float nx2 = nx1 + ww;
                ny1 = fminf(fmaxf(ny1, 0.0f), 1.0f);
                nx1 = fminf(fmaxf(nx1, 0.0f), 1.0f);
                ny2 = fminf(fmaxf(ny2, 0.0f), 1.0f);
                nx2 = fminf(fmaxf(nx2, 0.0f), 1.0f);

                int pos = atomicAdd(&g_cnt[img], 1);
                if (pos < NROI) {
                    g_cbox[img * NROI + pos]  = make_float4(ny1, nx1, ny2, nx2);
                    g_cmeta[img * NROI + pos] = make_float4(best, (float)bi, (float)r, 0.0f);
                }
            }
        }
    }

    // ---------------- Ticket: last block of this image runs the epilogue ----------------
    __syncthreads();
    if (t == 0) {
        __threadfence();
        int tick = atomicAdd(&g_done[img], 1);
        s_last = (tick == BPI - 1) ? 1 : 0;
    }
    __syncthreads();
    if (!s_last) return;
    __threadfence();   // acquire

    // ---------------- Epilogue (last block per image) ----------------
    Epi& ep = u.ep;
    const int base = img * NROI;
    const int M = min(g_cnt[img], MCAP);
    const int NK = (MCAP + BT - 1) / BT;   // 3

    if (t < NCLS) ep.ccount[t] = 0;
    for (int o = t; o < MAXI * 6; o += BT) ep.outbuf[o] = 0.0f;

    float r_score[NK]; short r_cls[NK]; short r_idx[NK];
    #pragma unroll
    for (int k = 0; k < NK; ++k) {
        int e = t + k * BT;
        if (e < M) {
            float4 m = g_cmeta[base + e];
            r_score[k] = m.x;
            r_cls[k]   = (short)m.y;
            r_idx[k]   = (short)m.z;
            ep.uscore[e] = m.x;
            ep.uidx[e]   = (short)m.z;
        }
    }
    __syncthreads();

    // rank sort (score desc, orig idx asc)
    #pragma unroll
    for (int k = 0; k < NK; ++k) {
        int e = t + k * BT;
        if (e >= M) continue;
        const float ks = r_score[k];
        const short ki = r_idx[k];
        int rank = 0;
        for (int j = 0; j < M; ++j) {
            float js = ep.uscore[j];
            rank += (js > ks) || (js == ks && ep.uidx[j] < ki);
        }
        float4 bx = g_cbox[base + e];
        ep.box[rank * 4 + 0] = bx.x;
        ep.box[rank * 4 + 1] = bx.y;
        ep.box[rank * 4 + 2] = bx.z;
        ep.box[rank * 4 + 3] = bx.w;
        ep.sscore[rank] = ks;
        ep.scls[rank]   = r_cls[k];
        ep.keep[rank]   = 1;
        atomicAdd(&ep.ccount[r_cls[k]], 1);
    }
    __syncthreads();

    if (t < NCLS) {
        int st = 0;
        for (int c = 0; c < t; ++c) st += ep.ccount[c];
        ep.cstart[t] = st;
    }
    __syncthreads();

    #pragma unroll
    for (int k = 0; k < NK; ++k) {
        int r = t + k * BT;
        if (r >= M) continue;
        short c = ep.scls[r];
        int w = 0;
        for (int j = 0; j < r; ++j) w += (ep.scls[j] == c);
        ep.bucket[ep.cstart[c] + w] = (short)r;
    }
    __syncthreads();

    // warp-per-class greedy NMS
    for (int c = wid; c < NCLS; c += 8) {
        const int st  = ep.cstart[c];
        const int cnt = ep.ccount[c];
        for (int a = 1; a < cnt; ++a) {
            int pa = ep.bucket[st + a];
            float ay1 = ep.box[pa * 4 + 0];
            float ax1 = ep.box[pa * 4 + 1];
            float ay2 = ep.box[pa * 4 + 2];
            float ax2 = ep.box[pa * 4 + 3];
            float aa = (ay2 - ay1) * (ax2 - ax1);
            bool hit = false;
            for (int q = lane; q < a; q += 32) {
                int pb = ep.bucket[st + q];
                if (ep.keep[pb]) {
                    float by1 = ep.box[pb * 4 + 0];
                    float bx1 = ep.box[pb * 4 + 1];
                    float by2 = ep.box[pb * 4 + 2];
                    float bx2 = ep.box[pb * 4 + 3];
                    float ab = (by2 - by1) * (bx2 - bx1);
                    float ih = fmaxf(fminf(ay2, by2) - fmaxf(ay1, by1), 0.0f);
                    float iw = fmaxf(fminf(ax2, bx2) - fmaxf(ax1, bx1), 0.0f);
                    float inter = ih * iw;
                    float iou = inter / fmaxf(aa + ab - inter, 1e-8f);
                    if (iou > 0.3f) hit = true;
                }
            }
            if (__ballot_sync(0xffffffffu, hit) && lane == 0) ep.keep[pa] = 0;
            __syncwarp();
        }
    }
    __syncthreads();

    // slot assignment + staged write
    #pragma unroll
    for (int k = 0; k < NK; ++k) {
        int e = t + k * BT;
        if (e >= M || !ep.keep[e]) continue;
        int slot = 0;
        for (int j = 0; j < e; ++j) slot += ep.keep[j];
        if (slot < MAXI) {
            ep.outbuf[slot * 6 + 0] = ep.box[e * 4 + 0];
            ep.outbuf[slot * 6 + 1] = ep.box[e * 4 + 1];
            ep.outbuf[slot * 6 + 2] = ep.box[e * 4 + 2];
            ep.outbuf[slot * 6 + 3] = ep.box[e * 4 + 3];
            ep.outbuf[slot * 6 + 4] = (float)ep.scls[e];
            ep.outbuf[slot * 6 + 5] = ep.sscore[e];
        }
    }
    __syncthreads();

    float* ob = out + (size_t)img * MAXI * 6;
    for (int o = t; o < MAXI * 6; o += BT) ob[o] = ep.outbuf[o];

    if (t == 0) { g_cnt[img] = 0; g_done[img] = 0; }   // reset for next replay
}

extern "C" void kernel_launch(void* const* d_in, const int* in_sizes, int n_in,
                              void* d_out, int out_size)
{
    const float* rois    = (const float*)d_in[0];
    const float* probs   = (const float*)d_in[1];
    const float* bbox    = (const float*)d_in[2];
    const float* std_dev = (const float*)d_in[3];
    float* out = (float*)d_out;
    det_kernel<<<BATCH * BPI, BT>>>(rois, probs, bbox, std_dev, out);
}

// round 9
// speedup vs baseline: 1.1600x; 1.1600x over previous
#include <cuda_runtime.h>
#include <math.h>

#define BATCH 32
#define NROI 1000
#define NCLS 81
#define MAXI 100
#define NTOT (BATCH * NROI)
#define BPI 32                 // blocks per image
#define RPB 32                 // ROIs per block (last block of image: 8)
#define BT 256                 // threads per block
#define MCAP 768               // max compacted entries per image

// compacted per-image lists + tickets (zero-init; reset each run by epilogue)
__device__ float4 g_cbox[NTOT];
__device__ float4 g_cmeta[NTOT];   // {score, cls, origidx, 0}
__device__ int    g_cnt[BATCH];
__device__ int    g_done[BATCH];

struct Epi {
    float uscore[MCAP];
    short uidx[MCAP];
    float box[MCAP * 4];
    float sscore[MCAP];
    short scls[MCAP];
    short bucket[MCAP];
    unsigned char keep[MCAP];
    int   ccount[NCLS];
    int   cstart[NCLS];
    float outbuf[MAXI * 6];
};

union SmemU {
    float probs[RPB * NCLS + 4];   // 10.4 KB tile (+ shift pad)
    Epi   ep;                      // ~26.9 KB epilogue state (dominates union)
};

__global__ __launch_bounds__(BT, 8)
void det_kernel(const float* __restrict__ rois,
                const float* __restrict__ probs,
                const float* __restrict__ bbox,
                const float* __restrict__ std_dev,
                float* __restrict__ out)
{
    __shared__ SmemU u;
    __shared__ int s_last;

    const int img = blockIdx.x / BPI;
    const int sub = blockIdx.x - img * BPI;
    const int t   = threadIdx.x;
    const int wid = t >> 5;
    const int lane = t & 31;

    const int row0  = sub * RPB;                      // first ROI of this block
    const int nrows = min(RPB, NROI - row0);          // 32, or 8 for last block

    // ---------------- Phase 1a: cooperative aligned tile load ----------------
    {
        const size_t s0 = ((size_t)img * NROI + row0) * NCLS;
        const int sh  = (int)(s0 & 3);
        const int NEL = nrows * NCLS;
        const int h   = (4 - sh) & 3;

        if (t < h) u.probs[sh + t] = probs[s0 + t];
        const int nvec = (NEL - h) >> 2;
        const float4* gp = (const float4*)(probs + s0 + h);
        float4* sp = (float4*)(u.probs + sh + h);
        for (int i = t; i < nvec; i += BT) sp[i] = gp[i];   // ~10 indep LDG.128/thread
        const int tl = NEL - h - 4 * nvec;
        if (t < tl) { int e = h + 4 * nvec + t; u.probs[sh + e] = probs[s0 + e]; }
        __syncthreads();

        // ------------- Phase 1b: thread-per-ROI argmax from smem -------------
        if (t < nrows) {
            const float* row = u.probs + sh + t * NCLS;   // stride 81 rows: conflict-free
            float b0 = row[0]; int i0 = 0;
            float b1 = row[1]; int i1 = 1;
            float b2 = row[2]; int i2 = 2;
            #pragma unroll 13
            for (int c = 3; c < 81; c += 3) {
                float v0 = row[c];
                float v1 = row[c + 1];
                float v2 = row[c + 2];
                if (v0 > b0) { b0 = v0; i0 = c; }
                if (v1 > b1) { b1 = v1; i1 = c + 1; }
                if (v2 > b2) { b2 = v2; i2 = c + 2; }
            }
            float best = b0; int bi = i0;
            if (b1 > best || (b1 == best && i1 < bi)) { best = b1; bi = i1; }
            if (b2 > best || (b2 == best && i2 < bi)) { best = b2; bi = i2; }

            if (bi > 0 && best >= 0.7f) {
                const int r = row0 + t;
                const size_t gri = (size_t)img * NROI + r;
                const float4 sd = *(const float4*)std_dev;
                const float4 dv = *(const float4*)(bbox + (gri * NCLS + bi) * 4);
                const float4 ro = *(const float4*)(rois + gri * 4);

                float d0 = dv.x * sd.x, d1 = dv.y * sd.y, d2 = dv.z * sd.z, d3 = dv.w * sd.w;
                float hh = ro.z - ro.x;
                float ww = ro.w - ro.y;
                float cy = ro.x + 0.5f * hh + d0 * hh;
                float cx = ro.y + 0.5f * ww + d1 * ww;
                hh *= expf(d2);
                ww *= expf(d3);
                float ny1 = cy - 0.5f * hh;
                float nx1 = cx - 0.5f * ww;
                float ny2 = ny1 + hh;
                float nx2 = nx1 + ww;
                ny1 = fminf(fmaxf(ny1, 0.0f), 1.0f);
                nx1 = fminf(fmaxf(nx1, 0.0f), 1.0f);
                ny2 = fminf(fmaxf(ny2, 0.0f), 1.0f);
                nx2 = fminf(fmaxf(nx2, 0.0f), 1.0f);

                int pos = atomicAdd(&g_cnt[img], 1);
                if (pos < NROI) {
                    g_cbox[img * NROI + pos]  = make_float4(ny1, nx1, ny2, nx2);
                    g_cmeta[img * NROI + pos] = make_float4(best, (float)bi, (float)r, 0.0f);
                }
            }
        }
    }

    // ---------------- Ticket: last block of this image runs the epilogue ----------------
    __syncthreads();
    if (t == 0) {
        __threadfence();
        int tick = atomicAdd(&g_done[img], 1);
        s_last = (tick == BPI - 1) ? 1 : 0;
    }
    __syncthreads();
    if (!s_last) return;
    __threadfence();   // acquire: all committed entries visible

    // ---------------- Epilogue (last block per image) ----------------
    Epi& ep = u.ep;
    const int base = img * NROI;
    const int M = min(g_cnt[img], MCAP);
    const int NK = (MCAP + BT - 1) / BT;   // 3

    if (t < NCLS) ep.ccount[t] = 0;
    for (int o = t; o < MAXI * 6; o += BT) ep.outbuf[o] = 0.0f;

    float r_score[NK]; short r_cls[NK]; short r_idx[NK];
    #pragma unroll
    for (int k = 0; k < NK; ++k) {
        int e = t + k * BT;
        if (e < M) {
            float4 m = g_cmeta[base + e];
            r_score[k] = m.x;
            r_cls[k]   = (short)m.y;
            r_idx[k]   = (short)m.z;
            ep.uscore[e] = m.x;
            ep.uidx[e]   = (short)m.z;
        }
    }
    __syncthreads();

    // rank sort (score desc, orig idx asc)
    #pragma unroll
    for (int k = 0; k < NK; ++k) {
        int e = t + k * BT;
        if (e >= M) continue;
        const float ks = r_score[k];
        const short ki = r_idx[k];
        int rank = 0;
        for (int j = 0; j < M; ++j) {
            float js = ep.uscore[j];
            rank += (js > ks) || (js == ks && ep.uidx[j] < ki);
        }
        float4 bx = g_cbox[base + e];
        ep.box[rank * 4 + 0] = bx.x;
        ep.box[rank * 4 + 1] = bx.y;
        ep.box[rank * 4 + 2] = bx.z;
        ep.box[rank * 4 + 3] = bx.w;
        ep.sscore[rank] = ks;
        ep.scls[rank]   = r_cls[k];
        ep.keep[rank]   = 1;
        atomicAdd(&ep.ccount[r_cls[k]], 1);
    }
    __syncthreads();

    if (t < NCLS) {
        int st = 0;
        for (int c = 0; c < t; ++c) st += ep.ccount[c];
        ep.cstart[t] = st;
    }
    __syncthreads();

    #pragma unroll
    for (int k = 0; k < NK; ++k) {
        int r = t + k * BT;
        if (r >= M) continue;
        short c = ep.scls[r];
        int w = 0;
        for (int j = 0; j < r; ++j) w += (ep.scls[j] == c);
        ep.bucket[ep.cstart[c] + w] = (short)r;
    }
    __syncthreads();

    // warp-per-class greedy NMS (short chains)
    for (int c = wid; c < NCLS; c += 8) {
        const int st  = ep.cstart[c];
        const int cnt = ep.ccount[c];
        for (int a = 1; a < cnt; ++a) {
            int pa = ep.bucket[st + a];
            float ay1 = ep.box[pa * 4 + 0];
            float ax1 = ep.box[pa * 4 + 1];
            float ay2 = ep.box[pa * 4 + 2];
            float ax2 = ep.box[pa * 4 + 3];
            float aa = (ay2 - ay1) * (ax2 - ax1);
            bool hit = false;
            for (int q = lane; q < a; q += 32) {
                int pb = ep.bucket[st + q];
                if (ep.keep[pb]) {
                    float by1 = ep.box[pb * 4 + 0];
                    float bx1 = ep.box[pb * 4 + 1];
                    float by2 = ep.box[pb * 4 + 2];
                    float bx2 = ep.box[pb * 4 + 3];
                    float ab = (by2 - by1) * (bx2 - bx1);
                    float ih = fmaxf(fminf(ay2, by2) - fmaxf(ay1, by1), 0.0f);
                    float iw = fmaxf(fminf(ax2, bx2) - fmaxf(ax1, bx1), 0.0f);
                    float inter = ih * iw;
                    float iou = inter / fmaxf(aa + ab - inter, 1e-8f);
                    if (iou > 0.3f) hit = true;
                }
            }
            if (__ballot_sync(0xffffffffu, hit) && lane == 0) ep.keep[pa] = 0;
            __syncwarp();
        }
    }
    __syncthreads();

    // slot assignment + staged write
    #pragma unroll
    for (int k = 0; k < NK; ++k) {
        int e = t + k * BT;
        if (e >= M || !ep.keep[e]) continue;
        int slot = 0;
        for (int j = 0; j < e; ++j) slot += ep.keep[j];
        if (slot < MAXI) {
            ep.outbuf[slot * 6 + 0] = ep.box[e * 4 + 0];
            ep.outbuf[slot * 6 + 1] = ep.box[e * 4 + 1];
            ep.outbuf[slot * 6 + 2] = ep.box[e * 4 + 2];
            ep.outbuf[slot * 6 + 3] = ep.box[e * 4 + 3];
            ep.outbuf[slot * 6 + 4] = (float)ep.scls[e];
            ep.outbuf[slot * 6 + 5] = ep.sscore[e];
        }
    }
    __syncthreads();

    float* ob = out + (size_t)img * MAXI * 6;
    for (int o = t; o < MAXI * 6; o += BT) ob[o] = ep.outbuf[o];

    if (t == 0) { g_cnt[img] = 0; g_done[img] = 0; }   // reset for next replay
}

extern "C" void kernel_launch(void* const* d_in, const int* in_sizes, int n_in,
                              void* d_out, int out_size)
{
    const float* rois    = (const float*)d_in[0];
    const float* probs   = (const float*)d_in[1];
    const float* bbox    = (const float*)d_in[2];
    const float* std_dev = (const float*)d_in[3];
    float* out = (float*)d_out;
    det_kernel<<<BATCH * BPI, BT>>>(rois, probs, bbox, std_dev, out);
}